// round 9
// baseline (speedup 1.0000x reference)
#include <cuda_runtime.h>

// ---------------------------------------------------------------------------
// Quantized LSTM, one speculative grid barrier per step (synchronous verify):
//  - GB=64 blocks x 640 threads, 16 batches/block (2 per thread) -> fewer
//    barrier participants, less arrival skew, more ILP per thread.
//  - block reduction: per-warp shfl max -> STS -> warp0 octet-shfl (no ATOMS).
//  - grid barrier: red.relaxed.max cells + red.release.add counter (no return
//    wait) -> poll ld.acquire -> read cells (per-step pre-zeroed).
//  - ALL scales speculative (k1, ka[4], k3, kh = previous step's exponents);
//    h written speculatively too. Verify derives true exponents from the
//    reduced extrema (activation scales analytically via monotonicity) and
//    dispatches tiered, globally-uniform fixups (local rewrite / 1-2 extra
//    grid rounds) on the rare miss.
// ---------------------------------------------------------------------------

#define GB       64
#define BPB      16
#define NT       640
#define T_STEPS  1024
#define NI       10
#define NH       20
#define NG       80
#define CSTRIDE  64              // 256B between cells
#define NCELL    16              // 0-7 main, 8 kh-fix, 9-10 full-fix, 11 retry

__device__ __align__(128) unsigned g_ctr0[32];
__device__ unsigned g_cells[T_STEPS * NCELL * CSTRIDE];

__global__ void qlstm_init() {
    int i = blockIdx.x * blockDim.x + threadIdx.x;   // 16384 = T_STEPS*NCELL
    if (i == 0) g_ctr0[0] = 0u;
    if (i < T_STEPS * NCELL) g_cells[i * CSTRIDE] = 0u;
}

__device__ __forceinline__ unsigned mapf(float f) {
    unsigned u = __float_as_uint(f);
    return (u & 0x80000000u) ? ~u : (u | 0x80000000u);
}
__device__ __forceinline__ float unmapf(unsigned u) {
    return __uint_as_float((u & 0x80000000u) ? (u & 0x7FFFFFFFu) : ~u);
}
__device__ __forceinline__ int po2k(float m) {
    m = fmaxf(m, 1e-8f);
    int e; float f = frexpf(m, &e);
    return (f == 0.5f) ? (e - 1) : e;
}
__device__ __forceinline__ float sc(int k)    { return __uint_as_float((unsigned)(k + 120) << 23); }
__device__ __forceinline__ float scinv(int k) { return __uint_as_float((unsigned)(134 - k) << 23); }
__device__ __forceinline__ float fq1(float x, float s, float inv) {
    float q = rintf(x * inv);
    q = fminf(fmaxf(q, -128.0f), 127.0f);
    return q * s;
}
__device__ __forceinline__ float sigm(float x) { return 1.0f / (1.0f + expf(-x)); }
__device__ __forceinline__ unsigned warp_max_u(unsigned v) {
#pragma unroll
    for (int o = 16; o; o >>= 1) v = max(v, __shfl_xor_sync(0xffffffffu, v, o));
    return v;
}
__device__ __forceinline__ void red_max_rlx(unsigned* p, unsigned v) {
    asm volatile("red.relaxed.gpu.max.u32 [%0],%1;" :: "l"(p), "r"(v) : "memory");
}
__device__ __forceinline__ void red_add_rel(unsigned* p, unsigned v) {
    asm volatile("red.release.gpu.add.u32 [%0],%1;" :: "l"(p), "r"(v) : "memory");
}
__device__ __forceinline__ unsigned ld_acq(const unsigned* p) {
    unsigned v; asm volatile("ld.acquire.gpu.u32 %0,[%1];" : "=r"(v) : "l"(p) : "memory"); return v;
}
__device__ __forceinline__ unsigned ld_rlx(const unsigned* p) {
    unsigned v; asm volatile("ld.relaxed.gpu.u32 %0,[%1];" : "=r"(v) : "l"(p) : "memory"); return v;
}

// warp0-collective grid round: lanes<ncontrib red their value into cell[lane],
// lane0 fires release-add, lanes<ncontrib poll acquire, then read back.
__device__ __forceinline__ unsigned grid_round(unsigned* cell0, unsigned myv, int ncontrib,
                                               unsigned tgt, int lane) {
    if (lane < ncontrib) red_max_rlx(cell0 + lane * CSTRIDE, myv);
    __syncwarp();
    if (lane == 0) red_add_rel(&g_ctr0[0], 1u);
    if (lane < ncontrib) { while (ld_acq(&g_ctr0[0]) < tgt) { } }
    __syncwarp();
    return (lane < ncontrib) ? ld_rlx(cell0 + lane * CSTRIDE) : 0u;
}

__global__ void __launch_bounds__(NT, 1) qlstm_main(
    const float* __restrict__ x,
    const float* __restrict__ Wih,
    const float* __restrict__ Whh,
    float* __restrict__ out)
{
    __shared__ __align__(16) float sh_h[BPB * NH];     // 320
    __shared__ __align__(16) float sh_x[BPB * NI];     // 160
    __shared__ float               sh_act[NG * BPB];   // 1280: act[row*16+batch]
    __shared__ unsigned            sh_wred[80];        // 0-31 kp, 32-63 kn, 64-71 tc, 72-79 hp
    __shared__ int                 sh_k[8];            // 0:k1 1-4:ka 5:k3 6:kh 7:code

    const int tid  = threadIdx.x;
    const int g    = tid >> 3;           // gate row 0..79
    const int b    = tid & 7;            // first batch; second = b+8
    const int gr   = tid / 160;          // gate group (warp-uniform; 5 warps/group)
    const int lane = tid & 31;
    const int wid  = tid >> 5;
    const int octp = (wid / 5) * 8 + (wid % 5);   // warp slot, group-octet layout

    if (tid < 80) sh_wred[tid] = 0u;
    if (tid < 7)  sh_k[tid] = 99;        // garbage predictions -> full miss at t=0
    if (tid == 7) sh_k[7] = 0;
    if (tid < BPB * NH) sh_h[tid] = 0.0f;
    __syncthreads();

    // ---- weight scale (block-local, once) ----
    {
        float wm = 0.0f;
        for (int k = tid; k < NG * NI; k += NT) wm = fmaxf(wm, fabsf(Wih[k]));
        for (int k = tid; k < NG * NH; k += NT) wm = fmaxf(wm, fabsf(Whh[k]));
        unsigned u = warp_max_u(__float_as_uint(wm));
        if (lane == 0) atomicMax(&sh_wred[0], u);
        __syncthreads();
    }
    int kw = po2k(__uint_as_float(sh_wred[0]));
    float ws = sc(kw), wsi = scinv(kw);
    __syncthreads();
    if (tid == 0) sh_wred[0] = 0u;
    __syncthreads();

    float wi[NI], wh[NH];
#pragma unroll
    for (int i2 = 0; i2 < NI; i2++) wi[i2] = fq1(Wih[g * NI + i2], ws, wsi);
#pragma unroll
    for (int j2 = 0; j2 < NH; j2++) wh[j2] = fq1(Whh[g * NH + j2], ws, wsi);

    // persistent state (tid<160: j = g, batches b and b+8)
    float c0 = 0.0f, c1 = 0.0f;
    float cp0 = 0.0f, cp1 = 0.0f;
    float tc0 = 0.0f, tc1 = 0.0f, oq0 = 0.0f, oq1 = 0.0f, hp0 = 0.0f, hp1 = 0.0f;
    float pre0 = 0.0f, pre1 = 0.0f;
    unsigned nbar = 0;

    const int sq  = tid - 480;                 // warps 15-19 stage x (160 threads)
    const int sxb = (sq >= 0) ? sq / NI : 0;
    const int sxi = (sq >= 0) ? sq % NI : 0;
    float xr = 0.0f;
    if (sq >= 0) {
        sh_x[sq] = x[((size_t)(blockIdx.x * BPB + sxb) * T_STEPS + 0) * NI + sxi];
        xr       = x[((size_t)(blockIdx.x * BPB + sxb) * T_STEPS + 1) * NI + sxi];
    }
    __syncthreads();

    for (int t = 0; t < T_STEPS; ++t) {
        const int k1p = sh_k[0], kap = sh_k[1 + gr], k3p = sh_k[5], khp = sh_k[6];

        // ===== phase B: pre (2 batches), warp extrema, speculative act =====
        {
            float a0 = 0.0f, a1 = 0.0f, b0s = 0.0f, b1s = 0.0f;
            const float2* px0 = reinterpret_cast<const float2*>(&sh_x[b * NI]);
            const float2* px1 = reinterpret_cast<const float2*>(&sh_x[(b + 8) * NI]);
            const float2* ph0 = reinterpret_cast<const float2*>(&sh_h[b * NH]);
            const float2* ph1 = reinterpret_cast<const float2*>(&sh_h[(b + 8) * NH]);
#pragma unroll
            for (int j = 0; j < NI / 2; j++) {
                float2 u0 = px0[j], u1 = px1[j];
                a0 = fmaf(u0.x, wi[2 * j], a0); b0s = fmaf(u0.y, wi[2 * j + 1], b0s);
                a1 = fmaf(u1.x, wi[2 * j], a1); b1s = fmaf(u1.y, wi[2 * j + 1], b1s);
            }
#pragma unroll
            for (int j = 0; j < NH / 2; j++) {
                float2 u0 = ph0[j], u1 = ph1[j];
                a0 = fmaf(u0.x, wh[2 * j], a0); b0s = fmaf(u0.y, wh[2 * j + 1], b0s);
                a1 = fmaf(u1.x, wh[2 * j], a1); b1s = fmaf(u1.y, wh[2 * j + 1], b1s);
            }
            pre0 = a0 + b0s; pre1 = a1 + b1s;
        }
        unsigned kp = warp_max_u(max(mapf(pre0), mapf(pre1)));
        unsigned kn = warp_max_u(max(mapf(-pre0), mapf(-pre1)));
        if (lane == 0) { sh_wred[octp] = kp; sh_wred[32 + octp] = kn; }
        {
            float s1 = sc(k1p), v1 = scinv(k1p);
            float sa = sc(kap), va = scinv(kap);
            float q0 = fq1(pre0, s1, v1), q1 = fq1(pre1, s1, v1);
            float ac0 = (gr == 2) ? tanhf(q0) : sigm(q0);
            float ac1 = (gr == 2) ? tanhf(q1) : sigm(q1);
            sh_act[g * BPB + b]     = fq1(ac0, sa, va);
            sh_act[g * BPB + b + 8] = fq1(ac1, sa, va);
        }
        __syncthreads();                                        // S1
        if (sq >= 0 && t + 1 < T_STEPS) sh_x[sq] = xr;

        // ===== phase C: c update, tanh, speculative h_pre & h =====
        if (tid < 160) {
            float iq0 = sh_act[g * BPB + b],        iq1 = sh_act[g * BPB + b + 8];
            float ff0 = sh_act[(20 + g) * BPB + b], ff1 = sh_act[(20 + g) * BPB + b + 8];
            float gg0 = sh_act[(40 + g) * BPB + b], gg1 = sh_act[(40 + g) * BPB + b + 8];
            oq0 = sh_act[(60 + g) * BPB + b];       oq1 = sh_act[(60 + g) * BPB + b + 8];
            cp0 = c0; cp1 = c1;
            c0 = ff0 * c0 + iq0 * gg0;
            c1 = ff1 * c1 + iq1 * gg1;
            tc0 = tanhf(c0); tc1 = tanhf(c1);
            float s3 = sc(k3p), v3 = scinv(k3p);
            hp0 = oq0 * fq1(tc0, s3, v3);
            hp1 = oq1 * fq1(tc1, s3, v3);
            float sh = sc(khp), vh = scinv(khp);
            float hq0 = fq1(hp0, sh, vh), hq1 = fq1(hp1, sh, vh);
            sh_h[b * NH + g] = hq0;
            sh_h[(b + 8) * NH + g] = hq1;
            out[((size_t)(blockIdx.x * BPB + b)     * T_STEPS + t) * NH + g] = hq0;
            out[((size_t)(blockIdx.x * BPB + b + 8) * T_STEPS + t) * NH + g] = hq1;
        }
        if (wid < 5) {
            unsigned a1 = warp_max_u(max(__float_as_uint(fabsf(tc0)), __float_as_uint(fabsf(tc1))));
            unsigned a2 = warp_max_u(max(__float_as_uint(fabsf(hp0)), __float_as_uint(fabsf(hp1))));
            if (lane == 0) { sh_wred[64 + wid] = a1; sh_wred[72 + wid] = a2; }
        }
        if (sq >= 0 && t + 2 < T_STEPS)
            xr = x[((size_t)(blockIdx.x * BPB + sxb) * T_STEPS + (t + 2)) * NI + sxi];
        __syncthreads();                                        // S2

        unsigned* cb = &g_cells[(size_t)t * NCELL * CSTRIDE];

        // ===== grid barrier + verify (warp 0) =====
        if (wid == 0) {
            unsigned vp = sh_wred[lane];
            unsigned vn = sh_wred[32 + lane];
            unsigned vt = (lane < 8) ? sh_wred[64 + lane] : 0u;
            unsigned vh = (lane < 8) ? sh_wred[72 + lane] : 0u;
#pragma unroll
            for (int o = 4; o; o >>= 1) {
                vp = max(vp, __shfl_down_sync(0xffffffffu, vp, o, 8));
                vn = max(vn, __shfl_down_sync(0xffffffffu, vn, o, 8));
                vt = max(vt, __shfl_down_sync(0xffffffffu, vt, o, 8));
                vh = max(vh, __shfl_down_sync(0xffffffffu, vh, o, 8));
            }
            unsigned p0 = __shfl_sync(0xffffffffu, vp, 0),  p1 = __shfl_sync(0xffffffffu, vp, 8);
            unsigned p2 = __shfl_sync(0xffffffffu, vp, 16), p3 = __shfl_sync(0xffffffffu, vp, 24);
            unsigned n0 = __shfl_sync(0xffffffffu, vn, 0),  n1 = __shfl_sync(0xffffffffu, vn, 8);
            unsigned n2 = __shfl_sync(0xffffffffu, vn, 16), n3 = __shfl_sync(0xffffffffu, vn, 24);
            unsigned tcm = __shfl_sync(0xffffffffu, vt, 0);
            unsigned hpm = __shfl_sync(0xffffffffu, vh, 0);
            unsigned myv = 0u;
            if (lane == 0) myv = p0;
            if (lane == 1) myv = p1;
            if (lane == 2) myv = p2;
            if (lane == 3) myv = p3;
            if (lane == 4) myv = n2;
            if (lane == 5) myv = max(max(n0, n1), max(n2, n3));
            if (lane == 6) myv = tcm;
            if (lane == 7) myv = hpm;
            nbar++;
            unsigned cv = grid_round(cb, myv, 8, nbar * GB, lane);

            unsigned kk = (lane < 4 || lane == 5) ? cv : 0u;
            kk = max(kk, __shfl_xor_sync(0xffffffffu, kk, 4));
            kk = max(kk, __shfl_xor_sync(0xffffffffu, kk, 2));
            kk = max(kk, __shfl_xor_sync(0xffffffffu, kk, 1));
            int k1 = po2k(unmapf(kk));
            float s1 = sc(k1), v1 = scinv(k1);
            float mng = unmapf(__shfl_sync(0xffffffffu, cv, 4));
            float myp = unmapf(cv);
            float a;
            if (lane == 2) {
                float q1 = fq1(myp, s1, v1), q2 = fq1(-mng, s1, v1);
                a = tanhf(fmaxf(q1, -q2));
            } else {
                a = sigm(fq1(myp, s1, v1));
            }
            int ka  = po2k(fabsf(a));
            int k3t = po2k(__uint_as_float(__shfl_sync(0xffffffffu, cv, 6)));
            int kht = po2k(__uint_as_float(__shfl_sync(0xffffffffu, cv, 7)));
            int old_ka = (lane < 4) ? sh_k[1 + lane] : 0;
            bool okl = (lane < 4) ? (ka == old_ka) : true;
            unsigned bm = __ballot_sync(0xffffffffu, okl);
            int k1old = sh_k[0], k3old = sh_k[5], khold = sh_k[6];
            int hit1 = (((bm & 0xFu) == 0xFu) && (k1 == k1old)) ? 1 : 0;
            int hit3 = (k3t == k3old) ? 1 : 0;
            int hith = (kht == khold) ? 1 : 0;
            int code = hit1 ? (hit3 ? (hith ? 0 : 1) : 2) : 3;
            if (lane < 4) sh_k[1 + lane] = ka;
            if (lane == 0) {
                sh_k[0] = k1;
                if (hit1) sh_k[5] = k3t;             // cell6 exact only when hit1
                if (hit1 && hit3) sh_k[6] = kht;     // cell7 exact only when hit1&hit3
                sh_k[7] = code;
            }
        }
        __syncthreads();                                        // S3

        const int code = sh_k[7];
        if (code == 0) continue;                                // full hit

        if (code == 1) {
            // kh miss only: hp exact -> local h/out rewrite
            if (tid < 160) {
                float sh_ = sc(sh_k[6]), vh_ = scinv(sh_k[6]);
                float hq0 = fq1(hp0, sh_, vh_), hq1 = fq1(hp1, sh_, vh_);
                sh_h[b * NH + g] = hq0; sh_h[(b + 8) * NH + g] = hq1;
                out[((size_t)(blockIdx.x * BPB + b)     * T_STEPS + t) * NH + g] = hq0;
                out[((size_t)(blockIdx.x * BPB + b + 8) * T_STEPS + t) * NH + g] = hq1;
            }
            __syncthreads();
        } else if (code == 2) {
            // k3 miss (k1/ka hit -> tc exact): redo hp with true k3, grid round for kh
            {
                float s3 = sc(sh_k[5]), v3 = scinv(sh_k[5]);
                if (tid < 160) { hp0 = oq0 * fq1(tc0, s3, v3); hp1 = oq1 * fq1(tc1, s3, v3); }
            }
            if (wid < 5) {
                unsigned a2 = warp_max_u(max(__float_as_uint(fabsf(hp0)), __float_as_uint(fabsf(hp1))));
                if (lane == 0) sh_wred[72 + wid] = a2;
            }
            __syncthreads();
            if (wid == 0) {
                unsigned vh = (lane < 8) ? sh_wred[72 + lane] : 0u;
#pragma unroll
                for (int o = 4; o; o >>= 1) vh = max(vh, __shfl_down_sync(0xffffffffu, vh, o, 8));
                unsigned myv = __shfl_sync(0xffffffffu, vh, 0);
                nbar++;
                unsigned cv = grid_round(cb + 8 * CSTRIDE, myv, 1, nbar * GB, lane);
                if (lane == 0) sh_k[6] = po2k(__uint_as_float(cv));
            }
            __syncthreads();
            if (tid < 160) {
                float sh_ = sc(sh_k[6]), vh_ = scinv(sh_k[6]);
                float hq0 = fq1(hp0, sh_, vh_), hq1 = fq1(hp1, sh_, vh_);
                sh_h[b * NH + g] = hq0; sh_h[(b + 8) * NH + g] = hq1;
                out[((size_t)(blockIdx.x * BPB + b)     * T_STEPS + t) * NH + g] = hq0;
                out[((size_t)(blockIdx.x * BPB + b + 8) * T_STEPS + t) * NH + g] = hq1;
            }
            __syncthreads();
        } else {
            // full miss: replay from exact pre / c_prev with true k1/ka
            {
                int k1 = sh_k[0], kat = sh_k[1 + gr];
                float s1 = sc(k1), v1 = scinv(k1);
                float sa = sc(kat), va = scinv(kat);
                float q0 = fq1(pre0, s1, v1), q1 = fq1(pre1, s1, v1);
                float ac0 = (gr == 2) ? tanhf(q0) : sigm(q0);
                float ac1 = (gr == 2) ? tanhf(q1) : sigm(q1);
                sh_act[g * BPB + b]     = fq1(ac0, sa, va);
                sh_act[g * BPB + b + 8] = fq1(ac1, sa, va);
            }
            __syncthreads();
            int k3g = sh_k[5];
            if (tid < 160) {
                float iq0 = sh_act[g * BPB + b],        iq1 = sh_act[g * BPB + b + 8];
                float ff0 = sh_act[(20 + g) * BPB + b], ff1 = sh_act[(20 + g) * BPB + b + 8];
                float gg0 = sh_act[(40 + g) * BPB + b], gg1 = sh_act[(40 + g) * BPB + b + 8];
                oq0 = sh_act[(60 + g) * BPB + b];       oq1 = sh_act[(60 + g) * BPB + b + 8];
                c0 = ff0 * cp0 + iq0 * gg0;
                c1 = ff1 * cp1 + iq1 * gg1;
                tc0 = tanhf(c0); tc1 = tanhf(c1);
                float s3 = sc(k3g), v3 = scinv(k3g);
                hp0 = oq0 * fq1(tc0, s3, v3);
                hp1 = oq1 * fq1(tc1, s3, v3);
            }
            if (wid < 5) {
                unsigned a1 = warp_max_u(max(__float_as_uint(fabsf(tc0)), __float_as_uint(fabsf(tc1))));
                unsigned a2 = warp_max_u(max(__float_as_uint(fabsf(hp0)), __float_as_uint(fabsf(hp1))));
                if (lane == 0) { sh_wred[64 + wid] = a1; sh_wred[72 + wid] = a2; }
            }
            __syncthreads();
            if (wid == 0) {
                unsigned vt = (lane < 8) ? sh_wred[64 + lane] : 0u;
                unsigned vh = (lane < 8) ? sh_wred[72 + lane] : 0u;
#pragma unroll
                for (int o = 4; o; o >>= 1) {
                    vt = max(vt, __shfl_down_sync(0xffffffffu, vt, o, 8));
                    vh = max(vh, __shfl_down_sync(0xffffffffu, vh, o, 8));
                }
                unsigned tcm = __shfl_sync(0xffffffffu, vt, 0);
                unsigned hpm = __shfl_sync(0xffffffffu, vh, 0);
                unsigned myv = (lane == 0) ? tcm : hpm;
                nbar++;
                unsigned cv = grid_round(cb + 9 * CSTRIDE, myv, 2, nbar * GB, lane);
                int kx = po2k(__uint_as_float(cv));
                int k3 = __shfl_sync(0xffffffffu, kx, 0);
                int kh = __shfl_sync(0xffffffffu, kx, 1);
                if (lane == 0) {
                    sh_k[5] = k3; sh_k[6] = kh;
                    sh_k[7] = (k3 == k3g) ? 0 : 1;   // retry flag
                }
            }
            __syncthreads();
            if (sh_k[7]) {   // k3 guess also missed: one more round
                float s3 = sc(sh_k[5]), v3 = scinv(sh_k[5]);
                if (tid < 160) { hp0 = oq0 * fq1(tc0, s3, v3); hp1 = oq1 * fq1(tc1, s3, v3); }
                if (wid < 5) {
                    unsigned a2 = warp_max_u(max(__float_as_uint(fabsf(hp0)), __float_as_uint(fabsf(hp1))));
                    if (lane == 0) sh_wred[72 + wid] = a2;
                }
                __syncthreads();
                if (wid == 0) {
                    unsigned vh = (lane < 8) ? sh_wred[72 + lane] : 0u;
#pragma unroll
                    for (int o = 4; o; o >>= 1) vh = max(vh, __shfl_down_sync(0xffffffffu, vh, o, 8));
                    unsigned myv = __shfl_sync(0xffffffffu, vh, 0);
                    nbar++;
                    unsigned cv = grid_round(cb + 11 * CSTRIDE, myv, 1, nbar * GB, lane);
                    if (lane == 0) sh_k[6] = po2k(__uint_as_float(cv));
                }
                __syncthreads();
            }
            if (tid < 160) {
                float sh_ = sc(sh_k[6]), vh_ = scinv(sh_k[6]);
                float hq0 = fq1(hp0, sh_, vh_), hq1 = fq1(hp1, sh_, vh_);
                sh_h[b * NH + g] = hq0; sh_h[(b + 8) * NH + g] = hq1;
                out[((size_t)(blockIdx.x * BPB + b)     * T_STEPS + t) * NH + g] = hq0;
                out[((size_t)(blockIdx.x * BPB + b + 8) * T_STEPS + t) * NH + g] = hq1;
            }
            __syncthreads();
        }
    }
}

extern "C" void kernel_launch(void* const* d_in, const int* in_sizes, int n_in,
                              void* d_out, int out_size) {
    (void)in_sizes; (void)n_in; (void)out_size;
    qlstm_init<<<32, 512>>>();
    qlstm_main<<<GB, NT>>>((const float*)d_in[0],
                           (const float*)d_in[1],
                           (const float*)d_in[2],
                           (float*)d_out);
}